// round 2
// baseline (speedup 1.0000x reference)
#include <cuda_runtime.h>

#define BATCH  50
#define NATOMS 512
#define NBONDS 4096
#define NHID   8
#define NLAYER 5

// Scratch (alloc-free rule: __device__ globals)
__device__ float g_delta[BATCH * NATOMS];
__device__ float g_delta_pi[BATCH * NATOMS];
__device__ float g_so[BATCH * NATOMS];
__device__ float g_ebond[BATCH];
__device__ int   g_owner[NATOMS * NATOMS];

__device__ __forceinline__ float sigmoidf(float x) {
    return 1.0f / (1.0f + expf(-x));
}

// Literal translation of _taper(r, rmin, rmax)
__device__ __forceinline__ float taperf(float e, float rmin, float rmax) {
    float r3  = (e > rmax) ? 1.0f : 0.0f;
    bool  ok  = (e <= rmax) && (e > rmin);
    float r2  = ok ? e : 0.0f;
    float r20 = ok ? 1.0f : 0.0f;
    float d   = rmin - rmax;
    float rterm = 1.0f / (d * d * d);
    float rm   = rmin * r20;
    float rd   = rm - r2;
    float trm1 = rm + 2.0f * r2 - 3.0f * rmax * r20;
    return rterm * rd * rd * trm1 + r3;
}

__global__ void k_zero() {
    int i = blockIdx.x * blockDim.x + threadIdx.x;
    if (i < BATCH * NATOMS) {
        g_delta[i]    = 0.0f;
        g_delta_pi[i] = 0.0f;
        g_so[i]       = 0.0f;
    }
    if (i < BATCH) g_ebond[i] = 0.0f;
    int stride = gridDim.x * blockDim.x;
    for (int j = i; j < NATOMS * NATOMS; j += stride) g_owner[j] = -1;
}

// Deduplicate bond pairs: owner[pair] = max bond index with that pair.
// Duplicated pairs have identical bop values (same atom positions), so any
// single-winner rule reproduces jax's .set() (contribute-once) semantics.
__global__ void k_dedup(const int* __restrict__ bdid) {
    int b = blockIdx.x * blockDim.x + threadIdx.x;
    if (b < NBONDS) {
        int i0 = bdid[2 * b + 0];
        int i1 = bdid[2 * b + 1];
        atomicMax(&g_owner[i0 * NATOMS + i1], b);
    }
}

__global__ void k_bonds(const float* __restrict__ x,
                        const float* __restrict__ cell,
                        const float* __restrict__ rcell,
                        const float* __restrict__ gp,
                        const float* __restrict__ bp,
                        const float* __restrict__ fwi,
                        const float* __restrict__ fw,
                        const float* __restrict__ fb,
                        const float* __restrict__ fwo,
                        const float* __restrict__ fbo,
                        const int* __restrict__ bdid) {
    __shared__ float s_wi[3 * NHID];
    __shared__ float s_w[NLAYER * NHID * NHID];
    __shared__ float s_b[NLAYER * NHID];
    __shared__ float s_wo[NHID];
    __shared__ float s_bo;
    __shared__ float s_red[8];  // per-warp partial sums (256 threads -> 8 warps)

    int t = threadIdx.x;
    for (int i = t; i < 3 * NHID; i += blockDim.x)            s_wi[i] = fwi[i];
    for (int i = t; i < NLAYER * NHID * NHID; i += blockDim.x) s_w[i] = fw[i];
    for (int i = t; i < NLAYER * NHID; i += blockDim.x)        s_b[i] = fb[i];
    for (int i = t; i < NHID; i += blockDim.x)                 s_wo[i] = fwo[i];
    if (t == 0) s_bo = fbo[0];
    __syncthreads();

    int b  = blockIdx.x * blockDim.x + t;   // bond index
    int bt = blockIdx.y;                    // batch index

    float eb_local = 0.0f;

    if (b < NBONDS) {
        int i0 = bdid[2 * b + 0];
        int i1 = bdid[2 * b + 1];

        const float* xb = x + (size_t)bt * NATOMS * 3;
        float d0 = xb[i0 * 3 + 0] - xb[i1 * 3 + 0];
        float d1 = xb[i0 * 3 + 1] - xb[i1 * 3 + 1];
        float d2 = xb[i0 * 3 + 2] - xb[i1 * 3 + 2];

        const float* R = rcell + (size_t)bt * 9;
        const float* C = cell  + (size_t)bt * 9;

        // vrf = vr @ rcell   (row-vector x matrix)
        float f0 = d0 * R[0] + d1 * R[3] + d2 * R[6];
        float f1 = d0 * R[1] + d1 * R[4] + d2 * R[7];
        float f2 = d0 * R[2] + d1 * R[5] + d2 * R[8];
        // exact wrap conditionals as in reference
        f0 = (f0 >  0.5f) ? f0 - 1.0f : ((f0 < -0.5f) ? f0 + 1.0f : f0);
        f1 = (f1 >  0.5f) ? f1 - 1.0f : ((f1 < -0.5f) ? f1 + 1.0f : f1);
        f2 = (f2 >  0.5f) ? f2 - 1.0f : ((f2 < -0.5f) ? f2 + 1.0f : f2);
        // vr = vrf @ cell
        float v0 = f0 * C[0] + f1 * C[3] + f2 * C[6];
        float v1 = f0 * C[1] + f1 * C[4] + f2 * C[7];
        float v2 = f0 * C[2] + f1 * C[5] + f2 * C[8];
        float r = sqrtf(v0 * v0 + v1 * v1 + v2 * v2);

        float botol = gp[6];
        float rosi = bp[0], ropi = bp[1], ropp = bp[2];
        float bo1 = bp[3], bo2 = bp[4], bo3 = bp[5], bo4 = bp[6];
        float bo5 = bp[7], bo6 = bp[8], Desi = bp[9];

        float e1 = (1.0f + botol) * expf(bo1 * powf(r / rosi, bo2));
        float e2 = expf(bo3 * powf(r / ropi, bo4));
        float e3 = expf(bo5 * powf(r / ropp, bo6));

        float rmax = 2.0f * botol;
        float bsi = taperf(e1, botol, rmax) * (e1 - botol);
        float bpi = taperf(e2, botol, rmax) * e2;
        float bpp = taperf(e3, botol, rmax) * e3;

        // MLP: 3 -> 8 -> (8->8)x5 -> 1, all sigmoid
        float h[NHID];
#pragma unroll
        for (int j = 0; j < NHID; j++) {
            h[j] = sigmoidf(bsi * s_wi[0 * NHID + j] +
                            bpi * s_wi[1 * NHID + j] +
                            bpp * s_wi[2 * NHID + j]);
        }
#pragma unroll
        for (int l = 0; l < NLAYER; l++) {
            float h2[NHID];
#pragma unroll
            for (int j = 0; j < NHID; j++) {
                float acc = s_b[l * NHID + j];
#pragma unroll
                for (int i = 0; i < NHID; i++)
                    acc += h[i] * s_w[l * NHID * NHID + i * NHID + j];
                h2[j] = sigmoidf(acc);
            }
#pragma unroll
            for (int j = 0; j < NHID; j++) h[j] = h2[j];
        }
        float o = s_bo;
#pragma unroll
        for (int i = 0; i < NHID; i++) o += h[i] * s_wo[i];
        float esi = sigmoidf(o);

        eb_local = -Desi * esi;

        // Per-atom scatter: only the owner bond of a pair contributes (set
        // semantics), and only when anything is nonzero (~1% of bonds).
        if ((bsi != 0.0f || bpi != 0.0f || bpp != 0.0f) &&
            g_owner[i0 * NATOMS + i1] == b) {
            float bop   = bsi + bpi + bpp;
            float bpipp = bpi + bpp;
            float* gd  = g_delta    + bt * NATOMS;
            float* gdp = g_delta_pi + bt * NATOMS;
            float* gs  = g_so       + bt * NATOMS;
            atomicAdd(&gd[i0], bop);
            atomicAdd(&gd[i1], bop);
            atomicAdd(&gdp[i0], bpipp);
            atomicAdd(&gdp[i1], bpipp);
            atomicAdd(&gs[i0], bsi);
            atomicAdd(&gs[i1], bsi);
        }
    }

    // Block reduction of eb_local (all threads in block share batch bt)
    unsigned mask = 0xFFFFFFFFu;
#pragma unroll
    for (int off = 16; off > 0; off >>= 1)
        eb_local += __shfl_down_sync(mask, eb_local, off);
    int warp = t >> 5;
    int lane = t & 31;
    if (lane == 0) s_red[warp] = eb_local;
    __syncthreads();
    if (warp == 0) {
        float v = (lane < (blockDim.x >> 5)) ? s_red[lane] : 0.0f;
#pragma unroll
        for (int off = 4; off > 0; off >>= 1)
            v += __shfl_down_sync(mask, v, off);
        if (lane == 0) atomicAdd(&g_ebond[bt], v);
    }
}

__global__ void k_atoms(const float* __restrict__ gp,
                        const float* __restrict__ sp_p,
                        const int* __restrict__ spec,
                        float* __restrict__ out) {
    __shared__ float s_red[16];
    int bt = blockIdx.x;
    int a  = threadIdx.x;  // 512 threads = NATOMS

    float lp1 = gp[0], ovun3 = gp[1], ovun4 = gp[2];
    float ovun6 = gp[3], ovun7 = gp[4], ovun8 = gp[5];

    int   sp    = spec[a];
    float val   = sp_p[sp * 5 + 0];
    float vale  = sp_p[sp * 5 + 1];
    float lp2   = sp_p[sp * 5 + 2];
    float ovun2 = sp_p[sp * 5 + 3];
    float ovun5 = sp_p[sp * 5 + 4];

    float Delta = g_delta[bt * NATOMS + a];
    float Dpi   = g_delta_pi[bt * NATOMS + a];
    float SO    = g_so[bt * NATOMS + a];

    float Nlp = 0.5f * (vale - val);
    float de  = 0.5f * (Delta - vale);
    float De  = -fmaxf(-ceilf(de), 0.0f);
    float tt  = 1.0f + de - De;
    float nlp = -De + expf(-lp1 * 4.0f * tt * tt);
    float Dlp = fmaxf(Nlp - nlp + 1.0f, 0.0f) - 1.0f;
    float Elone = lp2 * Dlp / (1.0f + expf(-75.0f * Dlp));

    float dlp   = Delta - val - Dlp / (1.0f + ovun3 * expf(ovun4 * Dpi));
    float denom = dlp + val;
    float otrm1 = 1.0f / ((denom != 0.0f) ? denom : 1e-8f);
    float Eover  = SO * otrm1 * dlp * sigmoidf(-ovun2 * dlp);
    float Eunder = -ovun5 * (1.0f - expf(ovun6 * dlp)) * sigmoidf(ovun2 * dlp) /
                   (1.0f + ovun7 * expf(ovun8 * Dpi));

    float e = Elone + Eover + Eunder;

    unsigned mask = 0xFFFFFFFFu;
#pragma unroll
    for (int off = 16; off > 0; off >>= 1)
        e += __shfl_down_sync(mask, e, off);
    int warp = a >> 5;
    int lane = a & 31;
    if (lane == 0) s_red[warp] = e;
    __syncthreads();
    if (warp == 0) {
        float v = (lane < 16) ? s_red[lane] : 0.0f;
#pragma unroll
        for (int off = 8; off > 0; off >>= 1)
            v += __shfl_down_sync(mask, v, off);
        if (lane == 0) out[bt] = g_ebond[bt] + v;
    }
}

extern "C" void kernel_launch(void* const* d_in, const int* in_sizes, int n_in,
                              void* d_out, int out_size) {
    const float* x     = (const float*)d_in[0];
    const float* cell  = (const float*)d_in[1];
    const float* rcell = (const float*)d_in[2];
    const float* sp_p  = (const float*)d_in[3];
    const float* gp    = (const float*)d_in[4];
    const float* bp    = (const float*)d_in[5];
    const float* fe_wi = (const float*)d_in[6];
    const float* fe_w  = (const float*)d_in[7];
    const float* fe_b  = (const float*)d_in[8];
    const float* fe_wo = (const float*)d_in[9];
    const float* fe_bo = (const float*)d_in[10];
    const int*   bdid  = (const int*)d_in[11];
    const int*   spec  = (const int*)d_in[12];
    float* out = (float*)d_out;

    k_zero<<<1024, 256>>>();
    k_dedup<<<(NBONDS + 255) / 256, 256>>>(bdid);
    dim3 g2((NBONDS + 255) / 256, BATCH);
    k_bonds<<<g2, 256>>>(x, cell, rcell, gp, bp,
                         fe_wi, fe_w, fe_b, fe_wo, fe_bo, bdid);
    k_atoms<<<BATCH, NATOMS>>>(gp, sp_p, spec, out);
}